// round 11
// baseline (speedup 1.0000x reference)
#include <cuda_runtime.h>
#include <cuda_bf16.h>
#include <math.h>
#include <stdint.h>

#define PN 4096            // 64*64 downsampled pixels/patches
#define CC 128
#define HI 128
#define NITEM 2

// ------------------------------------------------------ device scratch
__device__ __align__(128) float g_S[(size_t)NITEM * PN * PN];   // S0 -> L[p][q]
__device__ __align__(128) float g_T[(size_t)NITEM * PN * PN];   // T
__device__ __align__(128) float g_Bd[NITEM * CC * PN];
__device__ float g_n2[NITEM * PN];
__device__ float g_inorm[NITEM * PN];
__device__ float g_mm[NITEM * PN];
__device__ __align__(128) float g_bmax[(size_t)NITEM * PN * 128];  // [q][pb]
__device__ float g_cinv[NITEM * PN];
__device__ int   g_nnz[NITEM * PN];
__device__ __align__(128) short g_sp[(size_t)NITEM * PN * PN];  // sparse p idx
__device__ __align__(128) float g_se[(size_t)NITEM * PN * PN];  // sparse e*mm
__device__ __align__(128) float g_btr[NITEM * HI * HI * CC];    // b^T [yx][c]
__device__ __align__(128) float g_O[NITEM * HI * HI * CC];      // out^T [yx][c]
__device__ __align__(128) __nv_bfloat16 g_S0Ah[NITEM * PN * CC];
__device__ __align__(128) __nv_bfloat16 g_S0Al[NITEM * PN * CC];
__device__ __align__(128) __nv_bfloat16 g_S0Bh[NITEM * CC * PN];
__device__ __align__(128) __nv_bfloat16 g_S0Bl[NITEM * CC * PN];

// ------------------------------------------------------ PTX helpers
static __device__ __forceinline__ uint32_t smem_u32(const void* p) {
    uint32_t r;
    asm("{ .reg .u64 t; cvta.to.shared.u64 t, %1; cvt.u32.u64 %0, t; }" : "=r"(r) : "l"(p));
    return r;
}
// FFMA-imm (rt_SMSP=1, 2x FADD throughput); exact: a*1.0+b == a+b
static __device__ __forceinline__ float fadd1(float a, float b) {
    float d;
    asm("fma.rn.f32 %0, %1, 0f3F800000, %2;" : "=f"(d) : "f"(a), "f"(b));
    return d;
}
#define CPA(s, g) asm volatile("cp.async.cg.shared.global [%0], [%1], 16;" :: "r"(s), "l"(g))
#define CPC() asm volatile("cp.async.commit_group;" ::: "memory")
#define CPW1() asm volatile("cp.async.wait_group 1;" ::: "memory")
#define LDSM4(R, a) \
    asm volatile("ldmatrix.sync.aligned.m8n8.x4.shared.b16 {%0,%1,%2,%3}, [%4];" \
        : "=r"((R)[0]), "=r"((R)[1]), "=r"((R)[2]), "=r"((R)[3]) : "r"(a))
#define LDSM4T(R, a) \
    asm volatile("ldmatrix.sync.aligned.m8n8.x4.trans.shared.b16 {%0,%1,%2,%3}, [%4];" \
        : "=r"((R)[0]), "=r"((R)[1]), "=r"((R)[2]), "=r"((R)[3]) : "r"(a))
#define MMA16816(D, A, B) \
    asm volatile("mma.sync.aligned.m16n8k16.row.col.f32.bf16.bf16.f32 " \
        "{%0,%1,%2,%3},{%4,%5,%6,%7},{%8,%9},{%0,%1,%2,%3};" \
        : "+f"((D)[0]), "+f"((D)[1]), "+f"((D)[2]), "+f"((D)[3]) \
        : "r"((A)[0]), "r"((A)[1]), "r"((A)[2]), "r"((A)[3]), "r"((B)[0]), "r"((B)[1]))

// ------------------------------------------------------ pack downsample
__global__ void k_pack(const float* __restrict__ f, const float* __restrict__ b) {
    int idx = blockIdx.x * blockDim.x + threadIdx.x;
    int item = idx >> 19;
    int c = (idx >> 12) & 127;
    int q = idx & 4095;
    int y = q >> 6, x = q & 63;
    size_t base = ((size_t)item * CC + c) * HI * HI + (size_t)(2 * y) * HI + 2 * x;
    float vf = f[base];
    float vb = b[base];
    g_Bd[idx] = vb;
    __nv_bfloat16 h = __float2bfloat16(vf);
    g_S0Bh[idx] = h;
    g_S0Bl[idx] = __float2bfloat16(vf - __bfloat162float(h));
    h = __float2bfloat16(vb);
    int o = (item << 19) + q * CC + c;
    g_S0Ah[o] = h;
    g_S0Al[o] = __float2bfloat16(vb - __bfloat162float(h));
}

__global__ void k_stats(const float* __restrict__ mask) {
    int p = blockIdx.x * blockDim.x + threadIdx.x;
    int item = blockIdx.y;
    const float* Bd = g_Bd + item * CC * PN;
    float s = 0.f;
    for (int c = 0; c < CC; c++) {
        float v = Bd[c * PN + p];
        s += v * v;
    }
    g_n2[item * PN + p] = s;
    int ph = p >> 6, pw = p & 63;
    const float* m = mask + (size_t)item * HI * HI;
    float ms = 0.f;
    for (int dh = -1; dh <= 1; dh++)
        for (int dw = -1; dw <= 1; dw++) {
            int yy = ph + dh, xx = pw + dw;
            if ((unsigned)yy < 64u && (unsigned)xx < 64u)
                ms += m[(2 * yy) * HI + 2 * xx];
        }
    g_mm[item * PN + p] = (ms / 9.0f == 0.0f) ? 1.0f : 0.0f;
}

__global__ void k_norm() {
    int p = blockIdx.x * blockDim.x + threadIdx.x;
    int item = blockIdx.y;
    int ph = p >> 6, pw = p & 63;
    float s = 0.f;
    for (int dh = -1; dh <= 1; dh++)
        for (int dw = -1; dw <= 1; dw++) {
            int yy = ph + dh, xx = pw + dw;
            if ((unsigned)yy < 64u && (unsigned)xx < 64u)
                s += g_n2[item * PN + yy * 64 + xx];
        }
    g_inorm[item * PN + p] = rsqrtf(s + 0.1152f);
}

// =================================================== split-bf16 MMA GEMM (S0)
// 3-stage cp.async pipeline.
#define SA 10240      // 128 rows * 40 bf16 * 2B
#define SBZ 8704      // 32 rows * 136 bf16 * 2B
#define GSMEM (6 * SA + 6 * SBZ)   // 113664

__global__ void __launch_bounds__(256) mma_gemm(
    const __nv_bfloat16* __restrict__ Ah, const __nv_bfloat16* __restrict__ Al,
    const __nv_bfloat16* __restrict__ Bh, const __nv_bfloat16* __restrict__ Bl,
    float* __restrict__ C, int M, int N, int K,
    size_t sA, size_t sB, size_t sC) {
    extern __shared__ char smem[];
    uint32_t sb = smem_u32(smem);
    int tid = threadIdx.x;
    int lane = tid & 31, wid = tid >> 5;
    int warpM = wid >> 1, warpN = wid & 1;
    int m0 = blockIdx.y * 128, n0 = blockIdx.x * 128;
    int item = blockIdx.z;
    Ah += item * sA; Al += item * sA;
    Bh += item * sB; Bl += item * sB;
    C += item * sC;

    float acc[2][8][4];
#pragma unroll
    for (int i = 0; i < 2; i++)
#pragma unroll
        for (int j = 0; j < 8; j++)
#pragma unroll
            for (int v = 0; v < 4; v++) acc[i][j][v] = 0.f;

    auto load_stage = [&](int st, int kc) {
#pragma unroll
        for (int ma = 0; ma < 2; ma++) {
            const __nv_bfloat16* src = ma ? Al : Ah;
            uint32_t sbase = sb + (ma * 3 + st) * SA;
#pragma unroll
            for (int it = 0; it < 2; it++) {
                int idx = it * 256 + tid;
                int row = idx >> 2, seg = idx & 3;
                const void* g = src + (size_t)(m0 + row) * K + kc + seg * 8;
                CPA(sbase + (row * 40 + seg * 8) * 2, g);
            }
        }
#pragma unroll
        for (int mb = 0; mb < 2; mb++) {
            const __nv_bfloat16* src = mb ? Bl : Bh;
            uint32_t sbase = sb + 6 * SA + (mb * 3 + st) * SBZ;
#pragma unroll
            for (int it = 0; it < 2; it++) {
                int idx = it * 256 + tid;
                int row = idx >> 4, seg = idx & 15;
                const void* g = src + (size_t)(kc + row) * N + n0 + seg * 8;
                CPA(sbase + (row * 136 + seg * 8) * 2, g);
            }
        }
        CPC();
    };

    load_stage(0, 0);
    load_stage(1, 32);
    int NC = K >> 5;
    for (int c = 0; c < NC; c++) {
        CPW1();
        __syncthreads();
        int nc = c + 2;
        if (nc < NC) {
            int sidx = nc % 3;
            load_stage(sidx, nc << 5);
        } else {
            CPC();
        }
        int st = c % 3;
        uint32_t baseAh = sb + st * SA;
        uint32_t baseAl = sb + (3 + st) * SA;
        uint32_t baseBh = sb + 6 * SA + st * SBZ;
        uint32_t baseBl = sb + 6 * SA + (3 + st) * SBZ;
#pragma unroll
        for (int kk = 0; kk < 2; kk++) {
            uint32_t ah[2][4], al[2][4], bh[4][4], bl[4][4];
#pragma unroll
            for (int mb = 0; mb < 2; mb++) {
                uint32_t a = ((warpM * 32 + mb * 16 + (lane & 15)) * 40 + kk * 16 + (lane >> 4) * 8) * 2;
                LDSM4(ah[mb], baseAh + a);
                LDSM4(al[mb], baseAl + a);
            }
#pragma unroll
            for (int nb = 0; nb < 4; nb++) {
                uint32_t a = ((kk * 16 + (lane & 15)) * 136 + warpN * 64 + nb * 16 + (lane >> 4) * 8) * 2;
                LDSM4T(bh[nb], baseBh + a);
                LDSM4T(bl[nb], baseBl + a);
            }
#pragma unroll
            for (int mb = 0; mb < 2; mb++)
#pragma unroll
                for (int nb = 0; nb < 4; nb++)
#pragma unroll
                    for (int h = 0; h < 2; h++) {
                        float* D = acc[mb][nb * 2 + h];
                        MMA16816(D, ah[mb], &bh[nb][h * 2]);
                        MMA16816(D, ah[mb], &bl[nb][h * 2]);
                        MMA16816(D, al[mb], &bh[nb][h * 2]);
                    }
        }
    }
    int g = lane >> 2, tg = lane & 3;
#pragma unroll
    for (int mb = 0; mb < 2; mb++)
#pragma unroll
        for (int j = 0; j < 8; j++) {
            int row = m0 + warpM * 32 + mb * 16 + g;
            int col = n0 + warpN * 64 + j * 8 + tg * 2;
            float2 v0 = make_float2(acc[mb][j][0], acc[mb][j][1]);
            float2 v1 = make_float2(acc[mb][j][2], acc[mb][j][3]);
            *(float2*)&C[(size_t)row * N + col] = v0;
            *(float2*)&C[(size_t)(row + 8) * N + col] = v1;
        }
}

// ------------------------ vectorized 9-tap diagonal gather + normalize
__global__ __launch_bounds__(256) void k_tap9v() {
    int vid = blockIdx.x * 256 + threadIdx.x;
    int item = blockIdx.y;
    int p = vid >> 10;
    int q0 = (vid & 1023) << 2;
    int ph = p >> 6, pw = p & 63, qh = q0 >> 6, qw0 = q0 & 63;
    const float* S = g_S + (size_t)item * PN * PN;
    float4 acc = make_float4(0.f, 0.f, 0.f, 0.f);
    bool pm = (pw >= 1), pp_ = (pw <= 62);
#pragma unroll
    for (int dh = -1; dh <= 1; dh++) {
        if ((unsigned)(ph + dh) >= 64u || (unsigned)(qh + dh) >= 64u) continue;
        size_t a = (size_t)p * PN + q0 + (size_t)((long)dh * (64 * PN + 64));
        float4 Cv = *(const float4*)&S[a];
        acc.x = fadd1(Cv.x, acc.x); acc.y = fadd1(Cv.y, acc.y);
        acc.z = fadd1(Cv.z, acc.z); acc.w = fadd1(Cv.w, acc.w);
        if (pm) {
            float4 Mv = *(const float4*)&S[a - PN];
            float ml = (qw0 >= 1) ? S[a - PN - 1] : 0.f;
            acc.x = fadd1(ml, acc.x);   acc.y = fadd1(Mv.x, acc.y);
            acc.z = fadd1(Mv.y, acc.z); acc.w = fadd1(Mv.z, acc.w);
        }
        if (pp_) {
            float4 Pv = *(const float4*)&S[a + PN];
            float pr = (qw0 <= 59) ? S[a + PN + 4] : 0.f;
            acc.x = fadd1(Pv.y, acc.x); acc.y = fadd1(Pv.z, acc.y);
            acc.z = fadd1(Pv.w, acc.z); acc.w = fadd1(pr, acc.w);
        }
    }
    float in_ = g_inorm[item * PN + p];
    acc.x *= in_; acc.y *= in_; acc.z *= in_; acc.w *= in_;
    *(float4*)&g_T[(size_t)item * PN * PN + (size_t)p * PN + q0] = acc;
}

// ---------------- slow-path logit (exact round-10 semantics)
static __device__ float fz_slow(const float* T, int p, int q) {
    auto f1s = [&](int rr, int cc) -> float {
        size_t i = (size_t)rr * PN + cc;
        float s = T[i];
        if (rr > 0 && cc > 0) s = fadd1(T[i - PN - 1], s);
        if (rr < PN - 1 && cc < PN - 1) s = fadd1(T[i + PN + 1], s);
        return s;
    };
    if (q >= 64 && q < PN - 64 && p >= 64 && p < PN - 64)
        return fadd1(f1s(p - 64, q - 64), fadd1(f1s(p + 64, q + 64), f1s(p, q)));
    int rp = (p & 63) * 64 + (p >> 6);
    int rq = (q & 63) * 64 + (q >> 6);
    float s = 0.f;
#pragma unroll
    for (int j = -1; j <= 1; j++) {
        int tp = rp + j, tq = rq + j;
        if ((unsigned)tp < (unsigned)PN && (unsigned)tq < (unsigned)PN) {
            int pp = (tp & 63) * 64 + (tp >> 6);
            int qq = (tq & 63) * 64 + (tq >> 6);
            s = fadd1(f1s(pp, qq), s);
        }
    }
    return s;
}

// ---------------- fused fuse1+fuse2+logits: diagonal sliding-window walk.
// Row-major writes L[p][q] (coalesced) + exact per-(q, 32p-block) max g_bmax.
__global__ __launch_bounds__(128) void k_fz() {
    int lane = threadIdx.x & 31, wrp = threadIdx.x >> 5;
    int item = blockIdx.z;
    int warpQ0 = blockIdx.x * 512 + wrp * 128;
    int q0 = warpQ0 + lane * 4;
    int seg = blockIdx.y;                 // 32 segments of 128 p
    const float* T = g_T + (size_t)item * PN * PN;
    float* L = g_S + (size_t)item * PN * PN;
    const float* mm = g_mm + item * PN;
    __shared__ float bmt[4][4][128];      // [warp][pb_local][q_local]

    bool qInt = (q0 >= 68 && q0 <= PN - 72);
    int pbeg = seg * 128;

    float4 R00, R01, R02, R10, R11, R12, R20, R21, R22;
    float4 bm = make_float4(-1e30f, -1e30f, -1e30f, -1e30f);
    bool primed = false;

    for (int p = pbeg; p < pbeg + 128; p++) {
        float4 z;
        bool pInt = (p >= 65 && p <= PN - 66);
        if (qInt && pInt) {
            if (!primed) {
                R00 = *(const float4*)&T[(size_t)(p - 65) * PN + q0 - 64];
                R01 = *(const float4*)&T[(size_t)(p - 64) * PN + q0 - 64];
                R02 = *(const float4*)&T[(size_t)(p - 63) * PN + q0 - 64];
                R10 = *(const float4*)&T[(size_t)(p - 1) * PN + q0];
                R11 = *(const float4*)&T[(size_t)(p)     * PN + q0];
                R12 = *(const float4*)&T[(size_t)(p + 1) * PN + q0];
                R20 = *(const float4*)&T[(size_t)(p + 63) * PN + q0 + 64];
                R21 = *(const float4*)&T[(size_t)(p + 64) * PN + q0 + 64];
                R22 = *(const float4*)&T[(size_t)(p + 65) * PN + q0 + 64];
                primed = true;
            } else {
                R00 = R01; R01 = R02;
                R02 = *(const float4*)&T[(size_t)(p - 63) * PN + q0 - 64];
                R10 = R11; R11 = R12;
                R12 = *(const float4*)&T[(size_t)(p + 1) * PN + q0];
                R20 = R21; R21 = R22;
                R22 = *(const float4*)&T[(size_t)(p + 65) * PN + q0 + 64];
            }
            float eL0 = T[(size_t)(p - 65) * PN + q0 - 65];
            float eR0 = T[(size_t)(p - 63) * PN + q0 - 60];
            float eL1 = T[(size_t)(p - 1) * PN + q0 - 1];
            float eR1 = T[(size_t)(p + 1) * PN + q0 + 4];
            float eL2 = T[(size_t)(p + 63) * PN + q0 + 63];
            float eR2 = T[(size_t)(p + 65) * PN + q0 + 68];
            z.x = fadd1(eL0, fadd1(R01.x, fadd1(R02.y,
                  fadd1(eL1, fadd1(R11.x, fadd1(R12.y,
                  fadd1(eL2, fadd1(R21.x, R22.y))))))));
            z.y = fadd1(R00.x, fadd1(R01.y, fadd1(R02.z,
                  fadd1(R10.x, fadd1(R11.y, fadd1(R12.z,
                  fadd1(R20.x, fadd1(R21.y, R22.z))))))));
            z.z = fadd1(R00.y, fadd1(R01.z, fadd1(R02.w,
                  fadd1(R10.y, fadd1(R11.z, fadd1(R12.w,
                  fadd1(R20.y, fadd1(R21.z, R22.w))))))));
            z.w = fadd1(R00.z, fadd1(R01.w, fadd1(eR0,
                  fadd1(R10.z, fadd1(R11.w, fadd1(eR1,
                  fadd1(R20.z, fadd1(R21.w, eR2))))))));
        } else {
            primed = false;
            z.x = fz_slow(T, p, q0);
            z.y = fz_slow(T, p, q0 + 1);
            z.z = fz_slow(T, p, q0 + 2);
            z.w = fz_slow(T, p, q0 + 3);
        }
        float w = 10.f * mm[p];
        z.x *= w; z.y *= w; z.z *= w; z.w *= w;
        *(float4*)&L[(size_t)p * PN + q0] = z;
        bm.x = fmaxf(bm.x, z.x); bm.y = fmaxf(bm.y, z.y);
        bm.z = fmaxf(bm.z, z.z); bm.w = fmaxf(bm.w, z.w);
        if ((p & 31) == 31) {
            *(float4*)&bmt[wrp][(p >> 5) & 3][lane * 4] = bm;
            bm = make_float4(-1e30f, -1e30f, -1e30f, -1e30f);
        }
    }
    __syncwarp();
#pragma unroll
    for (int i = 0; i < 4; i++) {
        int ql = i * 32 + lane;
        int qq = warpQ0 + ql;
        float4 v = make_float4(bmt[wrp][0][ql], bmt[wrp][1][ql],
                               bmt[wrp][2][ql], bmt[wrp][3][ql]);
        *(float4*)&g_bmax[((size_t)item * PN + qq) * 128 + seg * 4] = v;
    }
}

// ---------------- hierarchical exp + sum + sparse compaction (warp per q)
__global__ __launch_bounds__(256) void k_esum() {
    int lane = threadIdx.x & 31, wid = threadIdx.x >> 5;
    int q = blockIdx.x * 8 + wid;
    int item = blockIdx.y;
    const float* L = g_S + (size_t)item * PN * PN;
    const float* mm = g_mm + item * PN;
    const float* bmr = g_bmax + ((size_t)item * PN + q) * 128;
    float4 mv = *(const float4*)&bmr[lane * 4];
    float m = fmaxf(fmaxf(mv.x, mv.y), fmaxf(mv.z, mv.w));
#pragma unroll
    for (int o = 16; o > 0; o >>= 1) m = fmaxf(m, __shfl_xor_sync(0xffffffffu, m, o));
    float mx = m;
    float thr = mx - 25.f;
    size_t base = ((size_t)(item * PN + q)) * (size_t)PN;
    int cnt = 0;
    float s = 0.f;
    for (int pb4 = 0; pb4 < 32; pb4++) {
        float bx = __shfl_sync(0xffffffffu, mv.x, pb4);
        float by = __shfl_sync(0xffffffffu, mv.y, pb4);
        float bz = __shfl_sync(0xffffffffu, mv.z, pb4);
        float bw = __shfl_sync(0xffffffffu, mv.w, pb4);
#pragma unroll
        for (int e = 0; e < 4; e++) {
            float bv = (e == 0) ? bx : (e == 1) ? by : (e == 2) ? bz : bw;
            if (bv <= thr) continue;
            int p = (pb4 * 4 + e) * 32 + lane;
            float d = L[(size_t)p * PN + q] - mx;
            bool live = (d > -25.f);
            float ev = live ? __expf(d) : 0.f;
            s += ev;
            float w = ev * mm[p];
            bool st = (w > 0.f);
            unsigned msk = __ballot_sync(0xffffffffu, st);
            if (st) {
                int rank = __popc(msk & ((1u << lane) - 1u));
                g_sp[base + cnt + rank] = (short)p;
                g_se[base + cnt + rank] = w;
            }
            cnt += __popc(msk);
        }
    }
#pragma unroll
    for (int o = 16; o > 0; o >>= 1) s += __shfl_xor_sync(0xffffffffu, s, o);
    if (lane == 0) {
        g_nnz[item * PN + q] = cnt;
        g_cinv[item * PN + q] = 1.f / s;
    }
}

// ---------------- transpose b -> btr[(Y*128+X)][c]
__global__ void k_btr(const float* __restrict__ b) {
    __shared__ float tile[32][33];
    int tx = threadIdx.x, ty = threadIdx.y;      // 32x8
    int item = blockIdx.z >> 2, ct = blockIdx.z & 3;
    int c0 = ct * 32;
    int Yp = blockIdx.y;
    int X0 = blockIdx.x * 32;
    const float* bi = b + (size_t)item * CC * HI * HI;
    for (int j = ty; j < 32; j += 8)
        tile[j][tx] = bi[(size_t)(c0 + j) * HI * HI + Yp * HI + X0 + tx];
    __syncthreads();
    float* dst = g_btr + ((size_t)item * HI * HI) * CC;
    for (int j = ty; j < 32; j += 8)
        dst[(size_t)(Yp * HI + X0 + j) * CC + c0 + tx] = tile[tx][j];
}

// ---------------- sparse deconv gather: block per output pixel (Y,X)
__global__ __launch_bounds__(128) void k_gather() {
    int yx = blockIdx.x;
    int Y = yx >> 7, X = yx & 127;
    int item = blockIdx.y;
    int c = threadIdx.x;
    const float* btr = g_btr + ((size_t)item * HI * HI) * CC;
    float acc = 0.f;
    int pky = (Y + 1) & 1, pkx = (X + 1) & 1;
#pragma unroll
    for (int a = 0; a < 2; a++) {
        int ky = pky + 2 * a;
        int yn = Y + 1 - ky;
        if (yn < 0) continue;
        int yy = yn >> 1;
        if (yy >= 64) continue;
#pragma unroll
        for (int bb = 0; bb < 2; bb++) {
            int kx = pkx + 2 * bb;
            int xn = X + 1 - kx;
            if (xn < 0) continue;
            int xx = xn >> 1;
            if (xx >= 64) continue;
            int q = yy * 64 + xx;
            int nnzq = g_nnz[item * PN + q];
            float cq = 0.25f * g_cinv[item * PN + q];
            size_t base = ((size_t)(item * PN + q)) * (size_t)PN;
            for (int i = 0; i < nnzq; i++) {
                int p = g_sp[base + i];
                float w = g_se[base + i] * cq;
                int ph = p >> 6, pw = p & 63;
                int Yp = 2 * ph - 1 + ky;
                int Xp = 2 * pw - 1 + kx;
                if ((unsigned)Yp < 128u && (unsigned)Xp < 128u)
                    acc += w * btr[(size_t)(Yp * HI + Xp) * CC + c];
            }
        }
    }
    g_O[((size_t)item * HI * HI + yx) * CC + c] = acc;
}

// ---------------- final transpose O[yx][c] -> out[c][yx]
__global__ void k_fin(float* __restrict__ out) {
    __shared__ float tile[32][33];
    int tx = threadIdx.x, ty = threadIdx.y;      // 32x8
    int yx0 = blockIdx.x * 32;
    int c0 = blockIdx.y * 32;
    int item = blockIdx.z;
    const float* src = g_O + ((size_t)item * HI * HI) * CC;
    for (int j = ty; j < 32; j += 8)
        tile[j][tx] = src[(size_t)(yx0 + j) * CC + c0 + tx];
    __syncthreads();
    float* dst = out + (size_t)item * CC * HI * HI;
    for (int j = ty; j < 32; j += 8)
        dst[(size_t)(c0 + j) * HI * HI + yx0 + tx] = tile[tx][j];
}

// ---------------------------------------------------------------- launcher
extern "C" void kernel_launch(void* const* d_in, const int* in_sizes, int n_in,
                              void* d_out, int out_size) {
    const float* f = (const float*)d_in[0];
    const float* b = (const float*)d_in[1];
    const float* mask = (const float*)d_in[2];
    float* out = (float*)d_out;

    float* pS;
    __nv_bfloat16 *pS0Ah, *pS0Al, *pS0Bh, *pS0Bl;
    cudaGetSymbolAddress((void**)&pS, g_S);
    cudaGetSymbolAddress((void**)&pS0Ah, g_S0Ah);
    cudaGetSymbolAddress((void**)&pS0Al, g_S0Al);
    cudaGetSymbolAddress((void**)&pS0Bh, g_S0Bh);
    cudaGetSymbolAddress((void**)&pS0Bl, g_S0Bl);

    cudaFuncSetAttribute(mma_gemm, cudaFuncAttributeMaxDynamicSharedMemorySize, GSMEM);

    k_pack<<<(NITEM * CC * PN) / 256, 256>>>(f, b);
    k_stats<<<dim3(PN / 256, NITEM), 256>>>(mask);
    k_norm<<<dim3(PN / 256, NITEM), 256>>>();
    k_btr<<<dim3(4, HI, NITEM * 4), dim3(32, 8)>>>(b);

    // S0[p][q] = sum_c Bd[c][p]*Fd[c][q]  (M=N=4096, K=128)
    mma_gemm<<<dim3(32, 32, NITEM), 256, GSMEM>>>(
        pS0Ah, pS0Al, pS0Bh, pS0Bl, pS, PN, PN, CC,
        (size_t)PN * CC, (size_t)CC * PN, (size_t)PN * PN);

    k_tap9v<<<dim3(PN * PN / 1024, NITEM), 256>>>();
    k_fz<<<dim3(8, 32, NITEM), 128>>>();
    k_esum<<<dim3(PN / 8, NITEM), 256>>>();

    k_gather<<<dim3(HI * HI, NITEM), 128>>>();
    k_fin<<<dim3(HI * HI / 32, CC / 32, NITEM), dim3(32, 8)>>>(out);
}

// round 12
// speedup vs baseline: 1.6473x; 1.6473x over previous
#include <cuda_runtime.h>
#include <cuda_bf16.h>
#include <math.h>
#include <stdint.h>

#define PN 4096            // 64*64 downsampled pixels/patches
#define CC 128
#define HI 128
#define NITEM 2
#define NSEG 8             // fz p-segments (512 p each)

// ------------------------------------------------------ device scratch
__device__ __align__(128) float g_S[(size_t)NITEM * PN * PN];   // S0 -> Lt
__device__ __align__(128) float g_T[(size_t)NITEM * PN * PN];   // T
__device__ __align__(128) float g_Bd[NITEM * CC * PN];
__device__ float g_n2[NITEM * PN];
__device__ float g_inorm[NITEM * PN];
__device__ float g_mm[NITEM * PN];
__device__ float g_cmaxp[NITEM * NSEG * PN];
__device__ float g_cinv[NITEM * PN];
__device__ int   g_nnz[NITEM * PN];
__device__ __align__(128) short g_sp[(size_t)NITEM * PN * PN];  // sparse p idx
__device__ __align__(128) float g_se[(size_t)NITEM * PN * PN];  // sparse e*mm
__device__ __align__(128) float g_btr[NITEM * HI * HI * CC];    // b^T [yx][c]
__device__ __align__(128) float g_O[NITEM * HI * HI * CC];      // out^T [yx][c]
__device__ __align__(128) __nv_bfloat16 g_S0Ah[NITEM * PN * CC];
__device__ __align__(128) __nv_bfloat16 g_S0Al[NITEM * PN * CC];
__device__ __align__(128) __nv_bfloat16 g_S0Bh[NITEM * CC * PN];
__device__ __align__(128) __nv_bfloat16 g_S0Bl[NITEM * CC * PN];

// ------------------------------------------------------ PTX helpers
static __device__ __forceinline__ uint32_t smem_u32(const void* p) {
    uint32_t r;
    asm("{ .reg .u64 t; cvta.to.shared.u64 t, %1; cvt.u32.u64 %0, t; }" : "=r"(r) : "l"(p));
    return r;
}
// FFMA-imm (rt_SMSP=1, 2x FADD throughput); exact: a*1.0+b == a+b
static __device__ __forceinline__ float fadd1(float a, float b) {
    float d;
    asm("fma.rn.f32 %0, %1, 0f3F800000, %2;" : "=f"(d) : "f"(a), "f"(b));
    return d;
}
#define CPA(s, g) asm volatile("cp.async.cg.shared.global [%0], [%1], 16;" :: "r"(s), "l"(g))
#define CPC() asm volatile("cp.async.commit_group;" ::: "memory")
#define CPW1() asm volatile("cp.async.wait_group 1;" ::: "memory")
#define LDSM4(R, a) \
    asm volatile("ldmatrix.sync.aligned.m8n8.x4.shared.b16 {%0,%1,%2,%3}, [%4];" \
        : "=r"((R)[0]), "=r"((R)[1]), "=r"((R)[2]), "=r"((R)[3]) : "r"(a))
#define LDSM4T(R, a) \
    asm volatile("ldmatrix.sync.aligned.m8n8.x4.trans.shared.b16 {%0,%1,%2,%3}, [%4];" \
        : "=r"((R)[0]), "=r"((R)[1]), "=r"((R)[2]), "=r"((R)[3]) : "r"(a))
#define MMA16816(D, A, B) \
    asm volatile("mma.sync.aligned.m16n8k16.row.col.f32.bf16.bf16.f32 " \
        "{%0,%1,%2,%3},{%4,%5,%6,%7},{%8,%9},{%0,%1,%2,%3};" \
        : "+f"((D)[0]), "+f"((D)[1]), "+f"((D)[2]), "+f"((D)[3]) \
        : "r"((A)[0]), "r"((A)[1]), "r"((A)[2]), "r"((A)[3]), "r"((B)[0]), "r"((B)[1]))

// ------------------------------------------------------ pack downsample
__global__ void k_pack(const float* __restrict__ f, const float* __restrict__ b) {
    int idx = blockIdx.x * blockDim.x + threadIdx.x;
    int item = idx >> 19;
    int c = (idx >> 12) & 127;
    int q = idx & 4095;
    int y = q >> 6, x = q & 63;
    size_t base = ((size_t)item * CC + c) * HI * HI + (size_t)(2 * y) * HI + 2 * x;
    float vf = f[base];
    float vb = b[base];
    g_Bd[idx] = vb;
    __nv_bfloat16 h = __float2bfloat16(vf);
    g_S0Bh[idx] = h;
    g_S0Bl[idx] = __float2bfloat16(vf - __bfloat162float(h));
    h = __float2bfloat16(vb);
    int o = (item << 19) + q * CC + c;
    g_S0Ah[o] = h;
    g_S0Al[o] = __float2bfloat16(vb - __bfloat162float(h));
}

__global__ void k_stats(const float* __restrict__ mask) {
    int p = blockIdx.x * blockDim.x + threadIdx.x;
    int item = blockIdx.y;
    const float* Bd = g_Bd + item * CC * PN;
    float s = 0.f;
    for (int c = 0; c < CC; c++) {
        float v = Bd[c * PN + p];
        s += v * v;
    }
    g_n2[item * PN + p] = s;
    int ph = p >> 6, pw = p & 63;
    const float* m = mask + (size_t)item * HI * HI;
    float ms = 0.f;
    for (int dh = -1; dh <= 1; dh++)
        for (int dw = -1; dw <= 1; dw++) {
            int yy = ph + dh, xx = pw + dw;
            if ((unsigned)yy < 64u && (unsigned)xx < 64u)
                ms += m[(2 * yy) * HI + 2 * xx];
        }
    g_mm[item * PN + p] = (ms / 9.0f == 0.0f) ? 1.0f : 0.0f;
}

__global__ void k_norm() {
    int p = blockIdx.x * blockDim.x + threadIdx.x;
    int item = blockIdx.y;
    int ph = p >> 6, pw = p & 63;
    float s = 0.f;
    for (int dh = -1; dh <= 1; dh++)
        for (int dw = -1; dw <= 1; dw++) {
            int yy = ph + dh, xx = pw + dw;
            if ((unsigned)yy < 64u && (unsigned)xx < 64u)
                s += g_n2[item * PN + yy * 64 + xx];
        }
    g_inorm[item * PN + p] = rsqrtf(s + 0.1152f);
}

// =================================================== split-bf16 MMA GEMM (S0)
// 3-stage cp.async pipeline.
#define SA 10240      // 128 rows * 40 bf16 * 2B
#define SBZ 8704      // 32 rows * 136 bf16 * 2B
#define GSMEM (6 * SA + 6 * SBZ)   // 113664

__global__ void __launch_bounds__(256) mma_gemm(
    const __nv_bfloat16* __restrict__ Ah, const __nv_bfloat16* __restrict__ Al,
    const __nv_bfloat16* __restrict__ Bh, const __nv_bfloat16* __restrict__ Bl,
    float* __restrict__ C, int M, int N, int K,
    size_t sA, size_t sB, size_t sC) {
    extern __shared__ char smem[];
    uint32_t sb = smem_u32(smem);
    int tid = threadIdx.x;
    int lane = tid & 31, wid = tid >> 5;
    int warpM = wid >> 1, warpN = wid & 1;
    int m0 = blockIdx.y * 128, n0 = blockIdx.x * 128;
    int item = blockIdx.z;
    Ah += item * sA; Al += item * sA;
    Bh += item * sB; Bl += item * sB;
    C += item * sC;

    float acc[2][8][4];
#pragma unroll
    for (int i = 0; i < 2; i++)
#pragma unroll
        for (int j = 0; j < 8; j++)
#pragma unroll
            for (int v = 0; v < 4; v++) acc[i][j][v] = 0.f;

    auto load_stage = [&](int st, int kc) {
#pragma unroll
        for (int ma = 0; ma < 2; ma++) {
            const __nv_bfloat16* src = ma ? Al : Ah;
            uint32_t sbase = sb + (ma * 3 + st) * SA;
#pragma unroll
            for (int it = 0; it < 2; it++) {
                int idx = it * 256 + tid;
                int row = idx >> 2, seg = idx & 3;
                const void* g = src + (size_t)(m0 + row) * K + kc + seg * 8;
                CPA(sbase + (row * 40 + seg * 8) * 2, g);
            }
        }
#pragma unroll
        for (int mb = 0; mb < 2; mb++) {
            const __nv_bfloat16* src = mb ? Bl : Bh;
            uint32_t sbase = sb + 6 * SA + (mb * 3 + st) * SBZ;
#pragma unroll
            for (int it = 0; it < 2; it++) {
                int idx = it * 256 + tid;
                int row = idx >> 4, seg = idx & 15;
                const void* g = src + (size_t)(kc + row) * N + n0 + seg * 8;
                CPA(sbase + (row * 136 + seg * 8) * 2, g);
            }
        }
        CPC();
    };

    load_stage(0, 0);
    load_stage(1, 32);
    int NC = K >> 5;
    for (int c = 0; c < NC; c++) {
        CPW1();
        __syncthreads();
        int nc = c + 2;
        if (nc < NC) {
            int sidx = nc % 3;
            load_stage(sidx, nc << 5);
        } else {
            CPC();
        }
        int st = c % 3;
        uint32_t baseAh = sb + st * SA;
        uint32_t baseAl = sb + (3 + st) * SA;
        uint32_t baseBh = sb + 6 * SA + st * SBZ;
        uint32_t baseBl = sb + 6 * SA + (3 + st) * SBZ;
#pragma unroll
        for (int kk = 0; kk < 2; kk++) {
            uint32_t ah[2][4], al[2][4], bh[4][4], bl[4][4];
#pragma unroll
            for (int mb = 0; mb < 2; mb++) {
                uint32_t a = ((warpM * 32 + mb * 16 + (lane & 15)) * 40 + kk * 16 + (lane >> 4) * 8) * 2;
                LDSM4(ah[mb], baseAh + a);
                LDSM4(al[mb], baseAl + a);
            }
#pragma unroll
            for (int nb = 0; nb < 4; nb++) {
                uint32_t a = ((kk * 16 + (lane & 15)) * 136 + warpN * 64 + nb * 16 + (lane >> 4) * 8) * 2;
                LDSM4T(bh[nb], baseBh + a);
                LDSM4T(bl[nb], baseBl + a);
            }
#pragma unroll
            for (int mb = 0; mb < 2; mb++)
#pragma unroll
                for (int nb = 0; nb < 4; nb++)
#pragma unroll
                    for (int h = 0; h < 2; h++) {
                        float* D = acc[mb][nb * 2 + h];
                        MMA16816(D, ah[mb], &bh[nb][h * 2]);
                        MMA16816(D, ah[mb], &bl[nb][h * 2]);
                        MMA16816(D, al[mb], &bh[nb][h * 2]);
                    }
        }
    }
    int g = lane >> 2, tg = lane & 3;
#pragma unroll
    for (int mb = 0; mb < 2; mb++)
#pragma unroll
        for (int j = 0; j < 8; j++) {
            int row = m0 + warpM * 32 + mb * 16 + g;
            int col = n0 + warpN * 64 + j * 8 + tg * 2;
            float2 v0 = make_float2(acc[mb][j][0], acc[mb][j][1]);
            float2 v1 = make_float2(acc[mb][j][2], acc[mb][j][3]);
            *(float2*)&C[(size_t)row * N + col] = v0;
            *(float2*)&C[(size_t)(row + 8) * N + col] = v1;
        }
}

// ------------------------ vectorized 9-tap diagonal gather + normalize
__global__ __launch_bounds__(256) void k_tap9v() {
    int vid = blockIdx.x * 256 + threadIdx.x;
    int item = blockIdx.y;
    int p = vid >> 10;
    int q0 = (vid & 1023) << 2;
    int ph = p >> 6, pw = p & 63, qh = q0 >> 6, qw0 = q0 & 63;
    const float* S = g_S + (size_t)item * PN * PN;
    float4 acc = make_float4(0.f, 0.f, 0.f, 0.f);
    bool pm = (pw >= 1), pp_ = (pw <= 62);
#pragma unroll
    for (int dh = -1; dh <= 1; dh++) {
        if ((unsigned)(ph + dh) >= 64u || (unsigned)(qh + dh) >= 64u) continue;
        size_t a = (size_t)p * PN + q0 + (size_t)((long)dh * (64 * PN + 64));
        float4 Cv = *(const float4*)&S[a];
        acc.x = fadd1(Cv.x, acc.x); acc.y = fadd1(Cv.y, acc.y);
        acc.z = fadd1(Cv.z, acc.z); acc.w = fadd1(Cv.w, acc.w);
        if (pm) {
            float4 Mv = *(const float4*)&S[a - PN];
            float ml = (qw0 >= 1) ? S[a - PN - 1] : 0.f;
            acc.x = fadd1(ml, acc.x);   acc.y = fadd1(Mv.x, acc.y);
            acc.z = fadd1(Mv.y, acc.z); acc.w = fadd1(Mv.z, acc.w);
        }
        if (pp_) {
            float4 Pv = *(const float4*)&S[a + PN];
            float pr = (qw0 <= 59) ? S[a + PN + 4] : 0.f;
            acc.x = fadd1(Pv.y, acc.x); acc.y = fadd1(Pv.z, acc.y);
            acc.z = fadd1(Pv.w, acc.z); acc.w = fadd1(pr, acc.w);
        }
    }
    float in_ = g_inorm[item * PN + p];
    acc.x *= in_; acc.y *= in_; acc.z *= in_; acc.w *= in_;
    *(float4*)&g_T[(size_t)item * PN * PN + (size_t)p * PN + q0] = acc;
}

// ---------------- fused fuse1 + fuse2 + column max (round-10 form, 8 segs)
// F1 computed on the fly from T; logits written TRANSPOSED into g_S;
// partial col max per 512-p segment.
__global__ __launch_bounds__(256) void k_fz() {
    int lane = threadIdx.x & 31, r = threadIdx.x >> 5;
    int q0 = blockIdx.x * 32;
    int q = q0 + lane;
    int seg = blockIdx.y;                 // NSEG p-segments of 512
    int item = blockIdx.z;
    const float* T = g_T + (size_t)item * PN * PN;
    float* Lt = g_S + (size_t)item * PN * PN;
    const float* mm = g_mm + item * PN;
    bool qIn = (q >= 64 && q < PN - 64);
    int rq = (q & 63) * 64 + (q >> 6);
    float mx = -1e30f;
    __shared__ float tile[32][33];
    __shared__ float red[8][32];

    auto f1 = [&](int rr, int cc) -> float {
        size_t i = (size_t)rr * PN + cc;
        float s = T[i];
        if (rr > 0 && cc > 0) s = fadd1(T[i - PN - 1], s);
        if (rr < PN - 1 && cc < PN - 1) s = fadd1(T[i + PN + 1], s);
        return s;
    };

    int pbeg = seg * 512, pend = pbeg + 512;
    for (int pt = pbeg; pt < pend; pt += 32) {
#pragma unroll
        for (int s4 = 0; s4 < 4; s4++) {
            int p = pt + s4 * 8 + r;
            float s;
            if (qIn && p >= 64 && p < PN - 64) {
                s = fadd1(f1(p - 64, q - 64), fadd1(f1(p + 64, q + 64), f1(p, q)));
            } else {
                int rp = (p & 63) * 64 + (p >> 6);
                s = 0.f;
#pragma unroll
                for (int j = -1; j <= 1; j++) {
                    int tp = rp + j, tq = rq + j;
                    if ((unsigned)tp < (unsigned)PN && (unsigned)tq < (unsigned)PN) {
                        int pp = (tp & 63) * 64 + (tp >> 6);
                        int qq = (tq & 63) * 64 + (tq >> 6);
                        s = fadd1(f1(pp, qq), s);
                    }
                }
            }
            float l = 10.f * s * mm[p];
            tile[s4 * 8 + r][lane] = l;
            mx = fmaxf(mx, l);
        }
        __syncthreads();
#pragma unroll
        for (int k = 0; k < 4; k++) {
            int qq = r * 4 + k;
            Lt[(size_t)(q0 + qq) * PN + pt + lane] = tile[lane][qq];
        }
        __syncthreads();
    }
    red[r][lane] = mx;
    __syncthreads();
    if (threadIdx.x < 32) {
        float m = red[0][threadIdx.x];
#pragma unroll
        for (int i = 1; i < 8; i++) m = fmaxf(m, red[i][threadIdx.x]);
        g_cmaxp[(item * NSEG + seg) * PN + q0 + threadIdx.x] = m;
    }
}

// ---------------- exp + sum + sparse compaction (warp per column q),
// float4-vectorized, with bit-exact segment skip.
__global__ __launch_bounds__(256) void k_esum() {
    int lane = threadIdx.x & 31, wid = threadIdx.x >> 5;
    int q = blockIdx.x * 8 + wid;
    int item = blockIdx.y;
    const float* Lt = g_S + (size_t)item * PN * PN + (size_t)q * PN;
    const float* mm = g_mm + item * PN;
    float segm[NSEG];
    float mx = -1e30f;
#pragma unroll
    for (int i = 0; i < NSEG; i++) {
        segm[i] = g_cmaxp[(item * NSEG + i) * PN + q];
        mx = fmaxf(mx, segm[i]);
    }
    float thr = mx - 25.f;
    size_t base = ((size_t)(item * PN + q)) * (size_t)PN;
    int cnt = 0;
    float s = 0.f;
#pragma unroll
    for (int seg = 0; seg < NSEG; seg++) {
        if (segm[seg] <= thr) continue;   // all e == 0 in this segment (exact)
        for (int p0 = seg * 512; p0 < seg * 512 + 512; p0 += 128) {
            float4 lv = *(const float4*)&Lt[p0 + lane * 4];
            float4 mv = *(const float4*)&mm[p0 + lane * 4];
            const float* lvp = (const float*)&lv;
            const float* mvp = (const float*)&mv;
#pragma unroll
            for (int j = 0; j < 4; j++) {
                float d = lvp[j] - mx;
                bool live = (d > -25.f);
                float e = live ? __expf(d) : 0.f;
                s += e;
                float w = e * mvp[j];
                bool st = (w > 0.f);
                unsigned msk = __ballot_sync(0xffffffffu, st);
                if (st) {
                    int rank = __popc(msk & ((1u << lane) - 1u));
                    g_sp[base + cnt + rank] = (short)(p0 + lane * 4 + j);
                    g_se[base + cnt + rank] = w;
                }
                cnt += __popc(msk);
            }
        }
    }
#pragma unroll
    for (int o = 16; o > 0; o >>= 1) s += __shfl_xor_sync(0xffffffffu, s, o);
    if (lane == 0) {
        g_nnz[item * PN + q] = cnt;
        g_cinv[item * PN + q] = 1.f / s;
    }
}

// ---------------- transpose b -> btr[(Y*128+X)][c]
__global__ void k_btr(const float* __restrict__ b) {
    __shared__ float tile[32][33];
    int tx = threadIdx.x, ty = threadIdx.y;      // 32x8
    int item = blockIdx.z >> 2, ct = blockIdx.z & 3;
    int c0 = ct * 32;
    int Yp = blockIdx.y;
    int X0 = blockIdx.x * 32;
    const float* bi = b + (size_t)item * CC * HI * HI;
    for (int j = ty; j < 32; j += 8)
        tile[j][tx] = bi[(size_t)(c0 + j) * HI * HI + Yp * HI + X0 + tx];
    __syncthreads();
    float* dst = g_btr + ((size_t)item * HI * HI) * CC;
    for (int j = ty; j < 32; j += 8)
        dst[(size_t)(Yp * HI + X0 + j) * CC + c0 + tx] = tile[tx][j];
}

// ---------------- sparse deconv gather: block per output pixel (Y,X)
__global__ __launch_bounds__(128) void k_gather() {
    int yx = blockIdx.x;
    int Y = yx >> 7, X = yx & 127;
    int item = blockIdx.y;
    int c = threadIdx.x;
    const float* btr = g_btr + ((size_t)item * HI * HI) * CC;
    float acc = 0.f;
    int pky = (Y + 1) & 1, pkx = (X + 1) & 1;
#pragma unroll
    for (int a = 0; a < 2; a++) {
        int ky = pky + 2 * a;
        int yn = Y + 1 - ky;
        if (yn < 0) continue;
        int yy = yn >> 1;
        if (yy >= 64) continue;
#pragma unroll
        for (int bb = 0; bb < 2; bb++) {
            int kx = pkx + 2 * bb;
            int xn = X + 1 - kx;
            if (xn < 0) continue;
            int xx = xn >> 1;
            if (xx >= 64) continue;
            int q = yy * 64 + xx;
            int nnzq = g_nnz[item * PN + q];
            float cq = 0.25f * g_cinv[item * PN + q];
            size_t base = ((size_t)(item * PN + q)) * (size_t)PN;
            for (int i = 0; i < nnzq; i++) {
                int p = g_sp[base + i];
                float w = g_se[base + i] * cq;
                int ph = p >> 6, pw = p & 63;
                int Yp = 2 * ph - 1 + ky;
                int Xp = 2 * pw - 1 + kx;
                if ((unsigned)Yp < 128u && (unsigned)Xp < 128u)
                    acc += w * btr[(size_t)(Yp * HI + Xp) * CC + c];
            }
        }
    }
    g_O[((size_t)item * HI * HI + yx) * CC + c] = acc;
}

// ---------------- final transpose O[yx][c] -> out[c][yx]
__global__ void k_fin(float* __restrict__ out) {
    __shared__ float tile[32][33];
    int tx = threadIdx.x, ty = threadIdx.y;      // 32x8
    int yx0 = blockIdx.x * 32;
    int c0 = blockIdx.y * 32;
    int item = blockIdx.z;
    const float* src = g_O + ((size_t)item * HI * HI) * CC;
    for (int j = ty; j < 32; j += 8)
        tile[j][tx] = src[(size_t)(yx0 + j) * CC + c0 + tx];
    __syncthreads();
    float* dst = out + (size_t)item * CC * HI * HI;
    for (int j = ty; j < 32; j += 8)
        dst[(size_t)(c0 + j) * HI * HI + yx0 + tx] = tile[tx][j];
}

// ---------------------------------------------------------------- launcher
extern "C" void kernel_launch(void* const* d_in, const int* in_sizes, int n_in,
                              void* d_out, int out_size) {
    const float* f = (const float*)d_in[0];
    const float* b = (const float*)d_in[1];
    const float* mask = (const float*)d_in[2];
    float* out = (float*)d_out;

    float* pS;
    __nv_bfloat16 *pS0Ah, *pS0Al, *pS0Bh, *pS0Bl;
    cudaGetSymbolAddress((void**)&pS, g_S);
    cudaGetSymbolAddress((void**)&pS0Ah, g_S0Ah);
    cudaGetSymbolAddress((void**)&pS0Al, g_S0Al);
    cudaGetSymbolAddress((void**)&pS0Bh, g_S0Bh);
    cudaGetSymbolAddress((void**)&pS0Bl, g_S0Bl);

    cudaFuncSetAttribute(mma_gemm, cudaFuncAttributeMaxDynamicSharedMemorySize, GSMEM);

    k_pack<<<(NITEM * CC * PN) / 256, 256>>>(f, b);
    k_stats<<<dim3(PN / 256, NITEM), 256>>>(mask);
    k_norm<<<dim3(PN / 256, NITEM), 256>>>();
    k_btr<<<dim3(4, HI, NITEM * 4), dim3(32, 8)>>>(b);

    // S0[p][q] = sum_c Bd[c][p]*Fd[c][q]  (M=N=4096, K=128)
    mma_gemm<<<dim3(32, 32, NITEM), 256, GSMEM>>>(
        pS0Ah, pS0Al, pS0Bh, pS0Bl, pS, PN, PN, CC,
        (size_t)PN * CC, (size_t)CC * PN, (size_t)PN * PN);

    k_tap9v<<<dim3(PN * PN / 1024, NITEM), 256>>>();
    k_fz<<<dim3(PN / 32, NSEG, NITEM), 256>>>();
    k_esum<<<dim3(PN / 8, NITEM), 256>>>();

    k_gather<<<dim3(HI * HI, NITEM), 128>>>();
    k_fin<<<dim3(HI * HI / 32, CC / 32, NITEM), dim3(32, 8)>>>(out);
}